// round 12
// baseline (speedup 1.0000x reference)
#include <cuda_runtime.h>

#define NQ      10
#define NLAYERS 5
#define NOUT    4

typedef unsigned long long ull;
typedef unsigned short u16;

// ======== compile-time GF(2) machinery: CNOT-ring deferral ========
struct GF { u16 r[NQ]; };
__host__ __device__ constexpr GF gf_id(){ GF g{}; for(int i=0;i<NQ;i++) g.r[i]=(u16)(1u<<i); return g; }
__host__ __device__ constexpr GF ring_C(){ GF g=gf_id(); for(int i=0;i<NQ;i++) g.r[(i+1)%NQ]=(u16)(g.r[(i+1)%NQ]^g.r[i]); return g; }
__host__ __device__ constexpr GF ring_D(){ GF g=gf_id(); for(int i=NQ-1;i>=0;i--) g.r[(i+1)%NQ]=(u16)(g.r[(i+1)%NQ]^g.r[i]); return g; }
__host__ __device__ constexpr GF gmul(GF a, GF b){ GF r{}; for(int k=0;k<NQ;k++){ u16 acc=0; for(int j=0;j<NQ;j++) if((a.r[k]>>j)&1) acc=(u16)(acc^b.r[j]); r.r[k]=acc; } return r; }
__host__ __device__ constexpr GF gpow(GF a, int t){ GF r=gf_id(); for(int i=0;i<t;i++) r=gmul(a,r); return r; }
__host__ __device__ constexpr u16 colq(GF a, int q){ u16 m=0; for(int k=0;k<NQ;k++) m=(u16)(m | ((u16)((a.r[k]>>q)&1)<<k)); return m; }
__host__ __device__ constexpr int cpopc(unsigned v){ int c=0; while(v){ c+=(int)(v&1u); v>>=1; } return c; }

__host__ __device__ constexpr u16 tab_m(int L, int q){ return colq(gpow(ring_D(), L), q); }   // pair mask
__host__ __device__ constexpr u16 tab_v(int L, int q){ return gpow(ring_C(), L).r[q]; }       // sign mask
__host__ __device__ constexpr u16 tab_w(int i){ return gpow(ring_C(), NLAYERS).r[i]; }        // measurement

// ======== packed f32x2 primitives ========
__device__ __forceinline__ ull fma2(ull a, ull b, ull c){
  ull d; asm("fma.rn.f32x2 %0, %1, %2, %3;" : "=l"(d) : "l"(a), "l"(b), "l"(c)); return d;
}
__device__ __forceinline__ ull mul2(ull a, ull b){
  ull d; asm("mul.rn.f32x2 %0, %1, %2;" : "=l"(d) : "l"(a), "l"(b)); return d;
}
__device__ __forceinline__ ull pack2(float lo, float hi){
  ull r; asm("mov.b64 %0, {%1, %2};" : "=l"(r) : "f"(lo), "f"(hi)); return r;
}
__device__ __forceinline__ void unpack2(ull v, float& lo, float& hi){
  asm("mov.b64 {%0, %1}, %2;" : "=f"(lo), "=f"(hi) : "l"(v));
}
__device__ __forceinline__ ull swap64(ull v){
  unsigned lo, hi; asm("mov.b64 {%0, %1}, %2;" : "=r"(lo), "=r"(hi) : "l"(v));
  ull r; asm("mov.b64 %0, {%1, %2};" : "=l"(r) : "r"(hi), "r"(lo)); return r;
}
template<int MH, bool SW>
__device__ __forceinline__ ull shfl_part(ull v){
  unsigned lo, hi; asm("mov.b64 {%0, %1}, %2;" : "=r"(lo), "=r"(hi) : "l"(v));
  lo = __shfl_xor_sync(0xffffffffu, lo, MH);
  hi = __shfl_xor_sync(0xffffffffu, hi, MH);
  ull r;
  if (SW) asm("mov.b64 %0, {%1, %2};" : "=l"(r) : "r"(hi), "r"(lo));
  else    asm("mov.b64 %0, {%1, %2};" : "=l"(r) : "r"(lo), "r"(hi));
  return r;
}

// ======== SU(2) sign-folded coefficients ========
// U = [[ (dR,dI), (oR,oI) ], [ (-oR,oI), (dR,-dI) ]]
// n.re = dR*sr - e*si + f*pr - oI*pi ; n.im = dR*si + e*sr + f*pi + oI*pr
// e = (-1)^sigma dI, f = (-1)^sigma oR ;
// sigma(lane,k,h) = par(vh&lane) ^ par(vlk&k) ^ (h&vb0)
struct Coef { ull dR2, E, nE, F, oI2, nOI2; };

__device__ __forceinline__ void slot_mac(ull& ore, ull& oim, ull sr, ull si, ull pr, ull pi, const Coef& c){
  ore = fma2(c.dR2, sr, fma2(c.nE, si, fma2(c.F, pr, mul2(c.nOI2, pi))));
  oim = fma2(c.dR2, si, fma2(c.E,  sr, fma2(c.F, pi, mul2(c.oI2,  pr))));
}

// ======== gate application over packed slots (KMAX bounds live support) ========
template<unsigned M, unsigned V, int KMAX>
struct GateApply {
  template<int K>
  static __device__ __forceinline__ void step(ull* sre, ull* sim, const Coef& cA, const Coef& cB){
    if constexpr (K < KMAX) {
      constexpr unsigned mh  = (M >> 5) & 31u;
      constexpr unsigned ml  = M & 31u;
      constexpr unsigned mlk = ml >> 1;
      constexpr bool     mb0 = (ml & 1u) != 0;
      constexpr unsigned vlk = (V & 31u) >> 1;
      constexpr int kb = K ^ (int)mlk;
      constexpr bool skip = (mlk != 0u) && (kb < K);
      if constexpr (!skip) {
        constexpr bool kpA = (cpopc(vlk & (unsigned)K) & 1) == 0;
        const Coef& cK = kpA ? cA : cB;
        if constexpr (mh != 0u) {
          // cross-lane gate
          ull prK = shfl_part<(int)mh, mb0>(sre[kb]);
          ull piK = shfl_part<(int)mh, mb0>(sim[kb]);
          if constexpr (mlk != 0u) {
            constexpr bool kpB = (cpopc(vlk & (unsigned)kb) & 1) == 0;
            const Coef& cB2 = kpB ? cA : cB;
            ull prB = shfl_part<(int)mh, mb0>(sre[K]);
            ull piB = shfl_part<(int)mh, mb0>(sim[K]);
            ull nrK, niK, nrB, niB;
            slot_mac(nrK, niK, sre[K],  sim[K],  prK, piK, cK);
            slot_mac(nrB, niB, sre[kb], sim[kb], prB, piB, cB2);
            sre[K] = nrK; sim[K] = niK; sre[kb] = nrB; sim[kb] = niB;
          } else {
            ull nr, ni;
            slot_mac(nr, ni, sre[K], sim[K], prK, piK, cK);
            sre[K] = nr; sim[K] = ni;
          }
        } else {
          // lane-local gate
          if constexpr (mlk != 0u) {
            constexpr bool kpB = (cpopc(vlk & (unsigned)kb) & 1) == 0;
            const Coef& cB2 = kpB ? cA : cB;
            ull ar = sre[K], ai = sim[K], br = sre[kb], bi = sim[kb];
            ull prK = mb0 ? swap64(br) : br;
            ull piK = mb0 ? swap64(bi) : bi;
            ull prB = mb0 ? swap64(ar) : ar;
            ull piB = mb0 ? swap64(ai) : ai;
            slot_mac(sre[K],  sim[K],  ar, ai, prK, piK, cK);
            slot_mac(sre[kb], sim[kb], br, bi, prB, piB, cB2);
          } else {
            // pair mask == local bit 0: partner = swapped self
            ull pr = swap64(sre[K]), pi = swap64(sim[K]);
            ull nr, ni;
            slot_mac(nr, ni, sre[K], sim[K], pr, pi, cK);
            sre[K] = nr; sim[K] = ni;
          }
        }
      }
      step<K + 1>(sre, sim, cA, cB);
    }
  }
};

// ======== per-gate driver (fused U = RY(phi) * RZ(theta) * RY(alpha)) ========
template<int T, int Q, int KMAX>
__device__ __forceinline__ void do_gate(ull* sre, ull* sim, int lane,
                                        float alpha, float theta, float phi){
  constexpr unsigned M = tab_m(T, Q);
  constexpr unsigned V = tab_v(T, Q);
  constexpr unsigned vh  = (V >> 5) & 31u;
  constexpr bool     vb0 = (V & 1u) != 0u;

  float sp, cp, sm, cm, st, ct;
  __sincosf(0.5f * (phi + alpha), &sp, &cp);
  __sincosf(0.5f * (phi - alpha), &sm, &cm);
  __sincosf(0.5f * theta,         &st, &ct);
  float dR = cp * ct;        // Re U00
  float dI = -cm * st;       // Im U00
  float oR = -sp * ct;       // Re U01
  float oI = -sm * st;       // Im U01

  float sg = 1.0f;
  if constexpr (vh != 0u)
    sg = (__popc((int)(vh & (unsigned)lane)) & 1) ? -1.0f : 1.0f;
  float e0 = sg * dI, f0 = sg * oR;
  float e1 = vb0 ? -e0 : e0;
  float f1 = vb0 ? -f0 : f0;

  Coef cA, cB;
  cA.dR2  = pack2(dR, dR);          cB.dR2  = cA.dR2;
  cA.oI2  = pack2(oI, oI);          cB.oI2  = cA.oI2;
  cA.nOI2 = pack2(-oI, -oI);        cB.nOI2 = cA.nOI2;
  cA.E    = pack2(e0, e1);          cB.nE   = cA.E;
  cA.nE   = pack2(-e0, -e1);        cB.E    = cA.nE;
  cA.F    = pack2(f0, f1);          cB.F    = pack2(-f0, -f1);

  GateApply<M, V, KMAX>::template step<0>(sre, sim, cA, cB);
}

// load angles for gate (T,Q) and apply with support bound KMAX
template<int T, int Q, int KMAX>
__device__ __forceinline__ void gate_tq(ull* sre, ull* sim, int lane,
                                        const float* __restrict__ xrow,
                                        const float* __restrict__ isc,
                                        const float* __restrict__ w){
  const float* iscL = isc + T * 2 * NQ;
  const float* wL   = w   + T * 2 * NQ;
  float xq    = __ldg(xrow + Q);
  float alpha = __ldg(iscL + Q) * xq;
  float theta = fmaf(__ldg(iscL + Q + NQ), xq, __ldg(wL + Q));
  float phi   = __ldg(wL + Q + NQ);
  do_gate<T, Q, KMAX>(sre, sim, lane, alpha, theta, phi);
}

template<int T, int Q>
__device__ __forceinline__ void layer_gates(ull* sre, ull* sim, int lane,
                                            const float* __restrict__ xrow,
                                            const float* __restrict__ isc,
                                            const float* __restrict__ w){
  if constexpr (Q < NQ) {
    gate_tq<T, Q, 16>(sre, sim, lane, xrow, isc, w);
    layer_gates<T, Q + 1>(sre, sim, lane, xrow, isc, w);
  }
}

// Layer 0: gates commute; apply cross-lane gates (q5..q9) FIRST while the
// support is confined to slot 0 (lane-bit gates never change the slot index),
// so each runs with KMAX=1. Then local gates with growing support bounds.
__device__ __forceinline__ void layer0(ull* sre, ull* sim, int lane,
                                       const float* __restrict__ xrow,
                                       const float* __restrict__ isc,
                                       const float* __restrict__ w){
  gate_tq<0, 5, 1>(sre, sim, lane, xrow, isc, w);
  gate_tq<0, 6, 1>(sre, sim, lane, xrow, isc, w);
  gate_tq<0, 7, 1>(sre, sim, lane, xrow, isc, w);
  gate_tq<0, 8, 1>(sre, sim, lane, xrow, isc, w);
  gate_tq<0, 9, 1>(sre, sim, lane, xrow, isc, w);
  gate_tq<0, 0, 1>(sre, sim, lane, xrow, isc, w);   // intra-slot, slot 0
  gate_tq<0, 1, 1>(sre, sim, lane, xrow, isc, w);   // pair (0,1)
  gate_tq<0, 2, 2>(sre, sim, lane, xrow, isc, w);   // pairs (0,2),(1,3)
  gate_tq<0, 3, 4>(sre, sim, lane, xrow, isc, w);
  gate_tq<0, 4, 8>(sre, sim, lane, xrow, isc, w);
}

template<int T>
__device__ __forceinline__ void all_layers(ull* sre, ull* sim, int lane,
                                           const float* __restrict__ xrow,
                                           const float* __restrict__ isc,
                                           const float* __restrict__ w){
  if constexpr (T < NLAYERS) {
    if constexpr (T == 0) layer0(sre, sim, lane, xrow, isc, w);
    else                  layer_gates<T, 0>(sre, sim, lane, xrow, isc, w);
    // CNOT ring deferred via compile-time masks — zero data movement
    all_layers<T + 1>(sre, sim, lane, xrow, isc, w);
  }
}

// ======== main kernel: one warp = one batch sample ========
// (128,6): 24 warps/SM, reg cap 85 — state(64)+coefs(14) hot set fits;
// ptxas remats/spills only cold prep temps.
__global__ void __launch_bounds__(128, 6)
qsim_kernel(const float* __restrict__ x, const float* __restrict__ isc,
            const float* __restrict__ w, const float* __restrict__ oscale,
            float* __restrict__ out, int batch){
  int gw   = (blockIdx.x * blockDim.x + threadIdx.x) >> 5;
  int lane = threadIdx.x & 31;
  if (gw >= batch) return;

  const float* xrow = x + gw * NQ;

  // phys index p = lane*32 + j ; slot k holds amps j=2k (lo) and j=2k+1 (hi)
  ull sre[16], sim[16];
#pragma unroll
  for (int k = 0; k < 16; k++) { sre[k] = 0ull; sim[k] = 0ull; }
  if (lane == 0) sre[0] = 0x3f800000ull;  // amp(0) = 1.0f

  all_layers<0>(sre, sim, lane, xrow, isc, w);

  // measurement: <Z_i> with sign mask W_i = row i of C^5 (deferred relabeling)
  constexpr unsigned W0 = tab_w(0), W1 = tab_w(1), W2 = tab_w(2), W3 = tab_w(3);
  constexpr int wl0 = (int)(W0 & 31u), wl1 = (int)(W1 & 31u);
  constexpr int wl2 = (int)(W2 & 31u), wl3 = (int)(W3 & 31u);
  float acc0 = 0.f, acc1 = 0.f, acc2 = 0.f, acc3 = 0.f;
#pragma unroll
  for (int k = 0; k < 16; k++) {
    ull p2 = fma2(sre[k], sre[k], mul2(sim[k], sim[k]));
    float plo, phi_;
    unpack2(p2, plo, phi_);
    acc0 += ((__popc(wl0 & (2*k)) & 1) ? -plo : plo) + ((__popc(wl0 & (2*k+1)) & 1) ? -phi_ : phi_);
    acc1 += ((__popc(wl1 & (2*k)) & 1) ? -plo : plo) + ((__popc(wl1 & (2*k+1)) & 1) ? -phi_ : phi_);
    acc2 += ((__popc(wl2 & (2*k)) & 1) ? -plo : plo) + ((__popc(wl2 & (2*k+1)) & 1) ? -phi_ : phi_);
    acc3 += ((__popc(wl3 & (2*k)) & 1) ? -plo : plo) + ((__popc(wl3 & (2*k+1)) & 1) ? -phi_ : phi_);
  }
  {
    constexpr int wh0 = (int)((W0 >> 5) & 31u), wh1 = (int)((W1 >> 5) & 31u);
    constexpr int wh2 = (int)((W2 >> 5) & 31u), wh3 = (int)((W3 >> 5) & 31u);
    if (__popc(wh0 & lane) & 1) acc0 = -acc0;
    if (__popc(wh1 & lane) & 1) acc1 = -acc1;
    if (__popc(wh2 & lane) & 1) acc2 = -acc2;
    if (__popc(wh3 & lane) & 1) acc3 = -acc3;
  }
#pragma unroll
  for (int o = 16; o; o >>= 1) {
    acc0 += __shfl_xor_sync(0xffffffffu, acc0, o);
    acc1 += __shfl_xor_sync(0xffffffffu, acc1, o);
    acc2 += __shfl_xor_sync(0xffffffffu, acc2, o);
    acc3 += __shfl_xor_sync(0xffffffffu, acc3, o);
  }
  if (lane == 0) {
    float4 r = make_float4(acc0 * oscale[0], acc1 * oscale[1],
                           acc2 * oscale[2], acc3 * oscale[3]);
    *reinterpret_cast<float4*>(out + gw * 4) = r;
  }
}

extern "C" void kernel_launch(void* const* d_in, const int* in_sizes, int n_in,
                              void* d_out, int out_size) {
  const float* x    = (const float*)d_in[0];  // (B, 10)
  const float* isc  = (const float*)d_in[1];  // (5, 20)
  const float* w    = (const float*)d_in[2];  // (5, 20)
  const float* oscl = (const float*)d_in[3];  // (4,)
  float*       out  = (float*)d_out;          // (B, 4)

  int batch   = in_sizes[0] / NQ;             // 4096
  int threads = 128;                          // 4 warps = 4 samples / block
  int blocks  = (batch * 32 + threads - 1) / threads;
  qsim_kernel<<<blocks, threads>>>(x, isc, w, oscl, out, batch);
}

// round 13
// speedup vs baseline: 2.0142x; 2.0142x over previous
#include <cuda_runtime.h>

#define NQ      10
#define NLAYERS 5
#define NOUT    4

typedef unsigned long long ull;
typedef unsigned short u16;

// ======== compile-time GF(2) machinery: CNOT-ring deferral ========
struct GF { u16 r[NQ]; };
__host__ __device__ constexpr GF gf_id(){ GF g{}; for(int i=0;i<NQ;i++) g.r[i]=(u16)(1u<<i); return g; }
__host__ __device__ constexpr GF ring_C(){ GF g=gf_id(); for(int i=0;i<NQ;i++) g.r[(i+1)%NQ]=(u16)(g.r[(i+1)%NQ]^g.r[i]); return g; }
__host__ __device__ constexpr GF ring_D(){ GF g=gf_id(); for(int i=NQ-1;i>=0;i--) g.r[(i+1)%NQ]=(u16)(g.r[(i+1)%NQ]^g.r[i]); return g; }
__host__ __device__ constexpr GF gmul(GF a, GF b){ GF r{}; for(int k=0;k<NQ;k++){ u16 acc=0; for(int j=0;j<NQ;j++) if((a.r[k]>>j)&1) acc=(u16)(acc^b.r[j]); r.r[k]=acc; } return r; }
__host__ __device__ constexpr GF gpow(GF a, int t){ GF r=gf_id(); for(int i=0;i<t;i++) r=gmul(a,r); return r; }
__host__ __device__ constexpr u16 colq(GF a, int q){ u16 m=0; for(int k=0;k<NQ;k++) m=(u16)(m | ((u16)((a.r[k]>>q)&1)<<k)); return m; }
__host__ __device__ constexpr int cpopc(unsigned v){ int c=0; while(v){ c+=(int)(v&1u); v>>=1; } return c; }

__host__ __device__ constexpr u16 tab_m(int L, int q){ return colq(gpow(ring_D(), L), q); }   // pair mask
__host__ __device__ constexpr u16 tab_v(int L, int q){ return gpow(ring_C(), L).r[q]; }       // sign mask
__host__ __device__ constexpr u16 tab_w(int i){ return gpow(ring_C(), NLAYERS).r[i]; }        // measurement

// ======== packed f32x2 primitives ========
__device__ __forceinline__ ull fma2(ull a, ull b, ull c){
  ull d; asm("fma.rn.f32x2 %0, %1, %2, %3;" : "=l"(d) : "l"(a), "l"(b), "l"(c)); return d;
}
__device__ __forceinline__ ull mul2(ull a, ull b){
  ull d; asm("mul.rn.f32x2 %0, %1, %2;" : "=l"(d) : "l"(a), "l"(b)); return d;
}
__device__ __forceinline__ ull pack2(float lo, float hi){
  ull r; asm("mov.b64 %0, {%1, %2};" : "=l"(r) : "f"(lo), "f"(hi)); return r;
}
__device__ __forceinline__ void unpack2(ull v, float& lo, float& hi){
  asm("mov.b64 {%0, %1}, %2;" : "=f"(lo), "=f"(hi) : "l"(v));
}
__device__ __forceinline__ ull swap64(ull v){
  unsigned lo, hi; asm("mov.b64 {%0, %1}, %2;" : "=r"(lo), "=r"(hi) : "l"(v));
  ull r; asm("mov.b64 %0, {%1, %2};" : "=l"(r) : "r"(hi), "r"(lo)); return r;
}
template<int MH, bool SW>
__device__ __forceinline__ ull shfl_part(ull v){
  unsigned lo, hi; asm("mov.b64 {%0, %1}, %2;" : "=r"(lo), "=r"(hi) : "l"(v));
  lo = __shfl_xor_sync(0xffffffffu, lo, MH);
  hi = __shfl_xor_sync(0xffffffffu, hi, MH);
  ull r;
  if (SW) asm("mov.b64 %0, {%1, %2};" : "=l"(r) : "r"(hi), "r"(lo));
  else    asm("mov.b64 %0, {%1, %2};" : "=l"(r) : "r"(lo), "r"(hi));
  return r;
}

// ======== SU(2) sign-folded coefficients ========
// U = [[ (dR,dI), (oR,oI) ], [ (-oR,oI), (dR,-dI) ]]
// n.re = dR*sr - e*si + f*pr - oI*pi ; n.im = dR*si + e*sr + f*pi + oI*pr
// e = (-1)^sigma dI, f = (-1)^sigma oR ;
// sigma(lane,k,h) = par(vh&lane) ^ par(vlk&k) ^ (h&vb0)
struct Coef { ull dR2, E, nE, F, oI2, nOI2; };

__device__ __forceinline__ void slot_mac(ull& ore, ull& oim, ull sr, ull si, ull pr, ull pi, const Coef& c){
  ore = fma2(c.dR2, sr, fma2(c.nE, si, fma2(c.F, pr, mul2(c.nOI2, pi))));
  oim = fma2(c.dR2, si, fma2(c.E,  sr, fma2(c.F, pi, mul2(c.oI2,  pr))));
}

// ======== gate application over packed slots (KMAX bounds live support) ========
template<unsigned M, unsigned V, int KMAX>
struct GateApply {
  template<int K>
  static __device__ __forceinline__ void step(ull* sre, ull* sim, const Coef& cA, const Coef& cB){
    if constexpr (K < KMAX) {
      constexpr unsigned mh  = (M >> 5) & 31u;
      constexpr unsigned ml  = M & 31u;
      constexpr unsigned mlk = ml >> 1;
      constexpr bool     mb0 = (ml & 1u) != 0;
      constexpr unsigned vlk = (V & 31u) >> 1;
      constexpr int kb = K ^ (int)mlk;
      constexpr bool skip = (mlk != 0u) && (kb < K);
      if constexpr (!skip) {
        constexpr bool kpA = (cpopc(vlk & (unsigned)K) & 1) == 0;
        const Coef& cK = kpA ? cA : cB;
        if constexpr (mh != 0u) {
          // cross-lane gate
          ull prK = shfl_part<(int)mh, mb0>(sre[kb]);
          ull piK = shfl_part<(int)mh, mb0>(sim[kb]);
          if constexpr (mlk != 0u) {
            constexpr bool kpB = (cpopc(vlk & (unsigned)kb) & 1) == 0;
            const Coef& cB2 = kpB ? cA : cB;
            ull prB = shfl_part<(int)mh, mb0>(sre[K]);
            ull piB = shfl_part<(int)mh, mb0>(sim[K]);
            ull nrK, niK, nrB, niB;
            slot_mac(nrK, niK, sre[K],  sim[K],  prK, piK, cK);
            slot_mac(nrB, niB, sre[kb], sim[kb], prB, piB, cB2);
            sre[K] = nrK; sim[K] = niK; sre[kb] = nrB; sim[kb] = niB;
          } else {
            ull nr, ni;
            slot_mac(nr, ni, sre[K], sim[K], prK, piK, cK);
            sre[K] = nr; sim[K] = ni;
          }
        } else {
          // lane-local gate
          if constexpr (mlk != 0u) {
            constexpr bool kpB = (cpopc(vlk & (unsigned)kb) & 1) == 0;
            const Coef& cB2 = kpB ? cA : cB;
            ull ar = sre[K], ai = sim[K], br = sre[kb], bi = sim[kb];
            ull prK = mb0 ? swap64(br) : br;
            ull piK = mb0 ? swap64(bi) : bi;
            ull prB = mb0 ? swap64(ar) : ar;
            ull piB = mb0 ? swap64(ai) : ai;
            slot_mac(sre[K],  sim[K],  ar, ai, prK, piK, cK);
            slot_mac(sre[kb], sim[kb], br, bi, prB, piB, cB2);
          } else {
            // pair mask == local bit 0: partner = swapped self
            ull pr = swap64(sre[K]), pi = swap64(sim[K]);
            ull nr, ni;
            slot_mac(nr, ni, sre[K], sim[K], pr, pi, cK);
            sre[K] = nr; sim[K] = ni;
          }
        }
      }
      step<K + 1>(sre, sim, cA, cB);
    }
  }
};

// ======== per-layer warp-parallel prep ========
// lane (l%10) computes the SU(2) entries for qubit (l%10) of layer T.
// All 10 gates' LDG+MUFU chains run concurrently in different lanes.
template<int T>
__device__ __forceinline__ void layer_prep(int lane,
                                           const float* __restrict__ xrow,
                                           const float* __restrict__ isc,
                                           const float* __restrict__ w,
                                           float& dR, float& dI, float& oR, float& oI){
  int q = lane % NQ;                       // lanes 10..31 compute harmless duplicates
  const float* iscL = isc + T * 2 * NQ;
  const float* wL   = w   + T * 2 * NQ;
  float xq    = __ldg(xrow + q);
  float alpha = __ldg(iscL + q) * xq;
  float theta = fmaf(__ldg(iscL + q + NQ), xq, __ldg(wL + q));
  float phi   = __ldg(wL + q + NQ);
  float sp, cp, sm, cm, st, ct;
  __sincosf(0.5f * (phi + alpha), &sp, &cp);
  __sincosf(0.5f * (phi - alpha), &sm, &cm);
  __sincosf(0.5f * theta,         &st, &ct);
  dR =  cp * ct;   // Re U00
  dI = -cm * st;   // Im U00
  oR = -sp * ct;   // Re U01
  oI = -sm * st;   // Im U01
}

// ======== per-gate driver: 4 scalar broadcasts + sign/pack only ========
template<int T, int Q, int KMAX>
__device__ __forceinline__ void gate_bc(ull* sre, ull* sim, int lane,
                                        float dRl, float dIl, float oRl, float oIl){
  constexpr unsigned M = tab_m(T, Q);
  constexpr unsigned V = tab_v(T, Q);
  constexpr unsigned vh  = (V >> 5) & 31u;
  constexpr bool     vb0 = (V & 1u) != 0u;

  float dR = __shfl_sync(0xffffffffu, dRl, Q);
  float dI = __shfl_sync(0xffffffffu, dIl, Q);
  float oR = __shfl_sync(0xffffffffu, oRl, Q);
  float oI = __shfl_sync(0xffffffffu, oIl, Q);

  float sg = 1.0f;
  if constexpr (vh != 0u)
    sg = (__popc((int)(vh & (unsigned)lane)) & 1) ? -1.0f : 1.0f;
  float e0 = sg * dI, f0 = sg * oR;
  float e1 = vb0 ? -e0 : e0;
  float f1 = vb0 ? -f0 : f0;

  Coef cA, cB;
  cA.dR2  = pack2(dR, dR);          cB.dR2  = cA.dR2;
  cA.oI2  = pack2(oI, oI);          cB.oI2  = cA.oI2;
  cA.nOI2 = pack2(-oI, -oI);        cB.nOI2 = cA.nOI2;
  cA.E    = pack2(e0, e1);          cB.nE   = cA.E;
  cA.nE   = pack2(-e0, -e1);        cB.E    = cA.nE;
  cA.F    = pack2(f0, f1);          cB.F    = pack2(-f0, -f1);

  GateApply<M, V, KMAX>::template step<0>(sre, sim, cA, cB);
}

template<int T, int Q>
__device__ __forceinline__ void layer_gates(ull* sre, ull* sim, int lane,
                                            float dRl, float dIl, float oRl, float oIl){
  if constexpr (Q < NQ) {
    gate_bc<T, Q, 16>(sre, sim, lane, dRl, dIl, oRl, oIl);
    layer_gates<T, Q + 1>(sre, sim, lane, dRl, dIl, oRl, oIl);
  }
}

// Layer 0: gates commute; apply cross-lane gates (q5..q9) FIRST while the
// support is confined to slot 0 (lane-bit gates never change the slot index),
// so each runs with KMAX=1. Then local gates with growing support bounds.
__device__ __forceinline__ void layer0(ull* sre, ull* sim, int lane,
                                       float dRl, float dIl, float oRl, float oIl){
  gate_bc<0, 5, 1>(sre, sim, lane, dRl, dIl, oRl, oIl);
  gate_bc<0, 6, 1>(sre, sim, lane, dRl, dIl, oRl, oIl);
  gate_bc<0, 7, 1>(sre, sim, lane, dRl, dIl, oRl, oIl);
  gate_bc<0, 8, 1>(sre, sim, lane, dRl, dIl, oRl, oIl);
  gate_bc<0, 9, 1>(sre, sim, lane, dRl, dIl, oRl, oIl);
  gate_bc<0, 0, 1>(sre, sim, lane, dRl, dIl, oRl, oIl);   // intra-slot, slot 0
  gate_bc<0, 1, 1>(sre, sim, lane, dRl, dIl, oRl, oIl);   // pair (0,1)
  gate_bc<0, 2, 2>(sre, sim, lane, dRl, dIl, oRl, oIl);   // pairs (0,2),(1,3)
  gate_bc<0, 3, 4>(sre, sim, lane, dRl, dIl, oRl, oIl);
  gate_bc<0, 4, 8>(sre, sim, lane, dRl, dIl, oRl, oIl);
}

template<int T>
__device__ __forceinline__ void all_layers(ull* sre, ull* sim, int lane,
                                           const float* __restrict__ xrow,
                                           const float* __restrict__ isc,
                                           const float* __restrict__ w){
  if constexpr (T < NLAYERS) {
    float dRl, dIl, oRl, oIl;
    layer_prep<T>(lane, xrow, isc, w, dRl, dIl, oRl, oIl);
    if constexpr (T == 0) layer0(sre, sim, lane, dRl, dIl, oRl, oIl);
    else                  layer_gates<T, 0>(sre, sim, lane, dRl, dIl, oRl, oIl);
    // CNOT ring deferred via compile-time masks — zero data movement
    all_layers<T + 1>(sre, sim, lane, xrow, isc, w);
  }
}

// ======== main kernel: one warp = one batch sample ========
__global__ void __launch_bounds__(128, 5)
qsim_kernel(const float* __restrict__ x, const float* __restrict__ isc,
            const float* __restrict__ w, const float* __restrict__ oscale,
            float* __restrict__ out, int batch){
  int gw   = (blockIdx.x * blockDim.x + threadIdx.x) >> 5;
  int lane = threadIdx.x & 31;
  if (gw >= batch) return;

  const float* xrow = x + gw * NQ;

  // phys index p = lane*32 + j ; slot k holds amps j=2k (lo) and j=2k+1 (hi)
  ull sre[16], sim[16];
#pragma unroll
  for (int k = 0; k < 16; k++) { sre[k] = 0ull; sim[k] = 0ull; }
  if (lane == 0) sre[0] = 0x3f800000ull;  // amp(0) = 1.0f

  all_layers<0>(sre, sim, lane, xrow, isc, w);

  // measurement: <Z_i> with sign mask W_i = row i of C^5 (deferred relabeling)
  constexpr unsigned W0 = tab_w(0), W1 = tab_w(1), W2 = tab_w(2), W3 = tab_w(3);
  constexpr int wl0 = (int)(W0 & 31u), wl1 = (int)(W1 & 31u);
  constexpr int wl2 = (int)(W2 & 31u), wl3 = (int)(W3 & 31u);
  float acc0 = 0.f, acc1 = 0.f, acc2 = 0.f, acc3 = 0.f;
#pragma unroll
  for (int k = 0; k < 16; k++) {
    ull p2 = fma2(sre[k], sre[k], mul2(sim[k], sim[k]));
    float plo, phi_;
    unpack2(p2, plo, phi_);
    acc0 += ((__popc(wl0 & (2*k)) & 1) ? -plo : plo) + ((__popc(wl0 & (2*k+1)) & 1) ? -phi_ : phi_);
    acc1 += ((__popc(wl1 & (2*k)) & 1) ? -plo : plo) + ((__popc(wl1 & (2*k+1)) & 1) ? -phi_ : phi_);
    acc2 += ((__popc(wl2 & (2*k)) & 1) ? -plo : plo) + ((__popc(wl2 & (2*k+1)) & 1) ? -phi_ : phi_);
    acc3 += ((__popc(wl3 & (2*k)) & 1) ? -plo : plo) + ((__popc(wl3 & (2*k+1)) & 1) ? -phi_ : phi_);
  }
  {
    constexpr int wh0 = (int)((W0 >> 5) & 31u), wh1 = (int)((W1 >> 5) & 31u);
    constexpr int wh2 = (int)((W2 >> 5) & 31u), wh3 = (int)((W3 >> 5) & 31u);
    if (__popc(wh0 & lane) & 1) acc0 = -acc0;
    if (__popc(wh1 & lane) & 1) acc1 = -acc1;
    if (__popc(wh2 & lane) & 1) acc2 = -acc2;
    if (__popc(wh3 & lane) & 1) acc3 = -acc3;
  }
#pragma unroll
  for (int o = 16; o; o >>= 1) {
    acc0 += __shfl_xor_sync(0xffffffffu, acc0, o);
    acc1 += __shfl_xor_sync(0xffffffffu, acc1, o);
    acc2 += __shfl_xor_sync(0xffffffffu, acc2, o);
    acc3 += __shfl_xor_sync(0xffffffffu, acc3, o);
  }
  if (lane == 0) {
    float4 r = make_float4(acc0 * oscale[0], acc1 * oscale[1],
                           acc2 * oscale[2], acc3 * oscale[3]);
    *reinterpret_cast<float4*>(out + gw * 4) = r;
  }
}

extern "C" void kernel_launch(void* const* d_in, const int* in_sizes, int n_in,
                              void* d_out, int out_size) {
  const float* x    = (const float*)d_in[0];  // (B, 10)
  const float* isc  = (const float*)d_in[1];  // (5, 20)
  const float* w    = (const float*)d_in[2];  // (5, 20)
  const float* oscl = (const float*)d_in[3];  // (4,)
  float*       out  = (float*)d_out;          // (B, 4)

  int batch   = in_sizes[0] / NQ;             // 4096
  int threads = 128;                          // 4 warps = 4 samples / block
  int blocks  = (batch * 32 + threads - 1) / threads;
  qsim_kernel<<<blocks, threads>>>(x, isc, w, oscl, out, batch);
}